// round 13
// baseline (speedup 1.0000x reference)
#include <cuda_runtime.h>
#include <cuda_fp16.h>
#include <math.h>
#include <stdint.h>

// Problem constants (fixed by the reference: B=4096, D=1024, N_CLASSES=64)
#define NB 4096
#define ND 1024

#define MARGIN    0.09f
#define SCALE_POS 2.0f
#define SCALE_NEG 40.0f
#define EPS_C     1e-5f
#define THRESH1   0.501f
#define THRESH2   0.531f

// -------------------- device scratch (no runtime allocation) --------------------
__device__ __half   g_sim16[(size_t)NB * NB];  // 32 MB similarity matrix (fp16)
__device__ float    g_t32[(size_t)NB * ND];    // 16 MB tf32-rounded feats
__device__ int      g_labels[NB];
__device__ uint32_t g_lab8[NB / 4];            // byte-packed labels (4 per word)
__device__ float    g_row[NB];

// -------------------- PTX helpers (plain sm_80 features only) --------------------
__device__ __forceinline__ uint32_t smem_u32(const void* p) {
    uint32_t a;
    asm("{ .reg .u64 t; cvta.to.shared.u64 t, %1; cvt.u32.u64 %0, t; }" : "=r"(a) : "l"(p));
    return a;
}
__device__ __forceinline__ void cp16(uint32_t s, const void* g) {
    asm volatile("cp.async.cg.shared.global [%0], [%1], 16;" :: "r"(s), "l"(g));
}
#define CP_COMMIT() asm volatile("cp.async.commit_group;" ::: "memory")
#define CP_WAIT2()  asm volatile("cp.async.wait_group 2;" ::: "memory")

__device__ __forceinline__ void ldsm4(uint32_t* r, uint32_t addr) {
    asm volatile("ldmatrix.sync.aligned.m8n8.x4.shared.b16 {%0,%1,%2,%3}, [%4];"
                 : "=r"(r[0]), "=r"(r[1]), "=r"(r[2]), "=r"(r[3]) : "r"(addr));
}
// m16n8k8 tf32: A = 4 regs, B = 2 regs, fp32 accum
__device__ __forceinline__ void mma_tf32(float* d, const uint32_t* a,
                                         uint32_t b0, uint32_t b1) {
    asm volatile(
        "mma.sync.aligned.m16n8k8.row.col.f32.tf32.tf32.f32 "
        "{%0,%1,%2,%3}, {%4,%5,%6,%7}, {%8,%9}, {%0,%1,%2,%3};"
        : "+f"(d[0]), "+f"(d[1]), "+f"(d[2]), "+f"(d[3])
        : "r"(a[0]), "r"(a[1]), "r"(a[2]), "r"(a[3]), "r"(b0), "r"(b1));
}
__device__ __forceinline__ uint32_t to_tf32(float x) {
    uint32_t o;
    asm("cvt.rna.tf32.f32 %0, %1;" : "=r"(o) : "f"(x));
    return o;
}

// -------------------- kernel 0: labels (int64/int32 auto-detect) + byte pack -------
__global__ void __launch_bounds__(256) labels_kernel(const int* __restrict__ lab) {
    __shared__ int sred[256];
    __shared__ int s_is64;
    int tid = threadIdx.x;
    int acc = 0;
    for (int i = tid; i < 2048; i += 256) acc |= lab[2 * i + 1];
    sred[tid] = acc;
    __syncthreads();
    for (int o = 128; o > 0; o >>= 1) {
        if (tid < o) sred[tid] |= sred[tid + o];
        __syncthreads();
    }
    if (tid == 0) s_is64 = (sred[0] == 0) ? 1 : 0;
    __syncthreads();
    int is64 = s_is64;
    for (int i = tid; i < NB; i += 256)
        g_labels[i] = is64 ? lab[2 * i] : lab[i];
    __syncthreads();
    for (int w = tid; w < NB / 4; w += 256) {
        uint32_t p = (uint32_t)(g_labels[4 * w] & 0xFF)
                   | ((uint32_t)(g_labels[4 * w + 1] & 0xFF) << 8)
                   | ((uint32_t)(g_labels[4 * w + 2] & 0xFF) << 16)
                   | ((uint32_t)(g_labels[4 * w + 3] & 0xFF) << 24);
        g_lab8[w] = p;
    }
}

// -------------------- kernel 1: f32 -> tf32 (round-to-nearest) --------------------
__global__ void __launch_bounds__(512) convert_kernel(const float* __restrict__ F) {
    size_t i = (size_t)blockIdx.x * 512 + threadIdx.x;   // one float4 per thread
    float4 v = reinterpret_cast<const float4*>(F)[i];
    uint4 o;
    o.x = to_tf32(v.x);
    o.y = to_tf32(v.y);
    o.z = to_tf32(v.z);
    o.w = to_tf32(v.w);
    reinterpret_cast<uint4*>(g_t32)[i] = o;
}

// -------------------- kernel 2: mma.sync tf32 symmetric GEMM --------------------
// 128x128 tiles, upper triangle + mirror; 4 warps x (64x64); BK=32 f32;
// 3-stage cp.async pipeline; kk-level ldsm/mma double buffering; fp16 stores.
#define STAGE_BYTES 32768          // A 16KB + B 16KB
#define NCHUNK 32
#define DYNSMEM (3 * STAGE_BYTES)  // 96 KB (epilogue reuses 64 KB of it)

__device__ __forceinline__ void load_chunk(int c, uint32_t stage,
                                           int rowA, int rowB, int tid) {
    const uint8_t* base = reinterpret_cast<const uint8_t*>(g_t32);
    size_t k0 = (size_t)c * 128;     // byte offset within 4096B row
    uint32_t sB = stage + 16384;
#pragma unroll
    for (int j = 0; j < 8; j++) {
        int u = (j << 7) + tid;          // 0..1023 16B units per operand
        int r = u >> 3;                  // row 0..127
        int ch = u & 7;                  // 16B chunk within 128B row
        uint32_t off = (uint32_t)((r << 7) + (ch << 4));
        uint32_t sw = off ^ ((off >> 3) & 0x70);
        cp16(stage + sw, base + (size_t)(rowA + r) * 4096 + k0 + (ch << 4));
        cp16(sB + sw,    base + (size_t)(rowB + r) * 4096 + k0 + (ch << 4));
    }
}

__global__ void __launch_bounds__(128, 2) gemm_mma_kernel() {
    extern __shared__ char dsm[];
    if ((int)blockIdx.x < (int)blockIdx.y) return;   // upper triangle only
    const int tid = threadIdx.x;
    const int lid = tid & 31;
    const int wid = tid >> 5;            // 0..3
    const int tileRow = blockIdx.y * 128;
    const int tileCol = blockIdx.x * 128;

    uint32_t SB = (smem_u32(dsm) + 127u) & ~127u;

    const int mRow0 = (wid >> 1) * 64;
    const int nCol0 = (wid & 1) * 64;

    const int aRow  = lid & 15;
    const int aKoff = ((lid >> 4) & 1) * 16;         // bytes
    const int bRow  = (lid & 7) + ((lid >> 4) << 3);
    const int bKoff = ((lid >> 3) & 1) * 16;         // bytes

    float acc[4][8][4];
#pragma unroll
    for (int mt = 0; mt < 4; mt++)
#pragma unroll
        for (int nt = 0; nt < 8; nt++)
#pragma unroll
            for (int q = 0; q < 4; q++) acc[mt][nt][q] = 0.0f;

    load_chunk(0, SB + 0 * STAGE_BYTES, tileRow, tileCol, tid); CP_COMMIT();
    load_chunk(1, SB + 1 * STAGE_BYTES, tileRow, tileCol, tid); CP_COMMIT();

    for (int c = 0; c < NCHUNK; c++) {
        if (c + 2 < NCHUNK)
            load_chunk(c + 2, SB + ((c + 2) % 3) * STAGE_BYTES, tileRow, tileCol, tid);
        CP_COMMIT();
        CP_WAIT2();
        __syncthreads();

        uint32_t sa = SB + (c % 3) * STAGE_BYTES;
        uint32_t sbm = sa + 16384;

        // kk-pipelined: ldsm for kk+1 issued before mma of kk
        uint32_t afrag[2][4][4];
        uint32_t bfrag[2][4][4];
#pragma unroll
        for (int mt = 0; mt < 4; mt++) {
            uint32_t off = (uint32_t)((mRow0 + mt * 16 + aRow) * 128 + aKoff);
            ldsm4(afrag[0][mt], sa + (off ^ ((off >> 3) & 0x70)));
        }
#pragma unroll
        for (int g = 0; g < 4; g++) {
            uint32_t off = (uint32_t)((nCol0 + g * 16 + bRow) * 128 + bKoff);
            ldsm4(bfrag[0][g], sbm + (off ^ ((off >> 3) & 0x70)));
        }
#pragma unroll
        for (int kk = 0; kk < 4; kk++) {
            int cur = kk & 1, nxt = cur ^ 1;
            if (kk < 3) {
#pragma unroll
                for (int mt = 0; mt < 4; mt++) {
                    uint32_t off = (uint32_t)((mRow0 + mt * 16 + aRow) * 128 +
                                              aKoff + (kk + 1) * 32);
                    ldsm4(afrag[nxt][mt], sa + (off ^ ((off >> 3) & 0x70)));
                }
#pragma unroll
                for (int g = 0; g < 4; g++) {
                    uint32_t off = (uint32_t)((nCol0 + g * 16 + bRow) * 128 +
                                              bKoff + (kk + 1) * 32);
                    ldsm4(bfrag[nxt][g], sbm + (off ^ ((off >> 3) & 0x70)));
                }
            }
#pragma unroll
            for (int mt = 0; mt < 4; mt++)
#pragma unroll
                for (int g = 0; g < 4; g++) {
                    mma_tf32(acc[mt][g * 2],     afrag[cur][mt],
                             bfrag[cur][g][0], bfrag[cur][g][1]);
                    mma_tf32(acc[mt][g * 2 + 1], afrag[cur][mt],
                             bfrag[cur][g][2], bfrag[cur][g][3]);
                }
        }
        __syncthreads();
    }

    // ---- epilogue: fragments -> XOR-swizzled SMEM -> fp16 normal + mirror stores ----
    float* C = reinterpret_cast<float*>(dsm);
#pragma unroll
    for (int mt = 0; mt < 4; mt++) {
        int r0 = mRow0 + mt * 16 + (lid >> 2);
#pragma unroll
        for (int nt = 0; nt < 8; nt++) {
            int cc = nCol0 + nt * 8 + (lid & 3) * 2;
            C[r0 * 128 + (cc ^ (r0 & 31))]       = acc[mt][nt][0];
            C[r0 * 128 + ((cc + 1) ^ (r0 & 31))] = acc[mt][nt][1];
            int r1 = r0 + 8;
            C[r1 * 128 + (cc ^ (r1 & 31))]       = acc[mt][nt][2];
            C[r1 * 128 + ((cc + 1) ^ (r1 & 31))] = acc[mt][nt][3];
        }
    }
    __syncthreads();

    // normal store: 8192 half2 units, 64 per thread
#pragma unroll 4
    for (int it = 0; it < 64; it++) {
        int idx = it * 128 + tid;
        int r = idx >> 6;                // 0..127
        int c2 = (idx & 63) * 2;         // even col
        float v0 = C[r * 128 + (c2 ^ (r & 31))];
        float v1 = C[r * 128 + ((c2 + 1) ^ (r & 31))];
        *reinterpret_cast<__half2*>(
            &g_sim16[(size_t)(tileRow + r) * NB + tileCol + c2]) =
            __floats2half2_rn(v0, v1);
    }
    if (blockIdx.x != blockIdx.y) {
#pragma unroll 4
        for (int it = 0; it < 64; it++) {
            int idx = it * 128 + tid;
            int j = idx >> 6;            // mirror row offset 0..127
            int i2 = (idx & 63) * 2;     // even mirror col
            float v0 = C[i2 * 128 + (j ^ (i2 & 31))];
            float v1 = C[(i2 + 1) * 128 + (j ^ ((i2 + 1) & 31))];
            *reinterpret_cast<__half2*>(
                &g_sim16[(size_t)(tileCol + j) * NB + tileRow + i2]) =
                __floats2half2_rn(v0, v1);
        }
    }
}

// -------------------- kernel 3: per-row reductions (fp16 sim, byte labels) ----------
__global__ void __launch_bounds__(256) row_kernel() {
    const int row = blockIdx.x;
    const int tid = threadIdx.x;
    const int lid = tid & 31;
    const int wrp = tid >> 5;

    __shared__ float wmx[8], wns[8], wps[8];
    __shared__ int   wnn[8], wnp[8];
    __shared__ float s_maxneg, s_negsum;
    __shared__ int   s_nneg;

    const uint4* srow = reinterpret_cast<const uint4*>(g_sim16 + (size_t)row * NB);
    const uint2* lab2 = reinterpret_cast<const uint2*>(g_lab8);
    const int rl = g_labels[row];
    const uint32_t rl4 = (uint32_t)(rl & 0xFF) * 0x01010101u;

    float s[16];
    uint32_t m_pc = 0;   // bit q: label == rl && s < 1-eps (pos candidate)

    float mx = -INFINITY, ns = 0.0f;
    int nn = 0;

#pragma unroll
    for (int it = 0; it < 2; it++) {
        uint4 raw = srow[it * 256 + tid];            // 8 halves
        uint2 lw = lab2[it * 256 + tid];             // 8 byte-labels
        uint32_t eq0 = __vcmpeq4(lw.x, rl4);         // 0xFF per matching byte
        uint32_t eq1 = __vcmpeq4(lw.y, rl4);
        nn += __popc(~eq0 & 0x01010101u) + __popc(~eq1 & 0x01010101u);
        float2 f0 = __half22float2(*reinterpret_cast<const __half2*>(&raw.x));
        float2 f1 = __half22float2(*reinterpret_cast<const __half2*>(&raw.y));
        float2 f2 = __half22float2(*reinterpret_cast<const __half2*>(&raw.z));
        float2 f3 = __half22float2(*reinterpret_cast<const __half2*>(&raw.w));
        float sv[8] = {f0.x, f0.y, f1.x, f1.y, f2.x, f2.y, f3.x, f3.y};
#pragma unroll
        for (int q = 0; q < 8; q++) {
            s[it * 8 + q] = sv[q];
            uint32_t eqw = (q < 4) ? eq0 : eq1;
            bool iseq = (eqw >> ((q & 3) * 8)) & 1;
            if (!iseq) {
                ns += __expf(SCALE_NEG * sv[q]);
                mx = fmaxf(mx, sv[q]);
            } else if (sv[q] < (1.0f - EPS_C)) {
                m_pc |= (1u << (it * 8 + q));
            }
        }
    }

#pragma unroll
    for (int o = 16; o > 0; o >>= 1) {
        mx = fmaxf(mx, __shfl_xor_sync(0xFFFFFFFFu, mx, o));
        ns += __shfl_xor_sync(0xFFFFFFFFu, ns, o);
        nn += __shfl_xor_sync(0xFFFFFFFFu, nn, o);
    }
    if (lid == 0) { wmx[wrp] = mx; wns[wrp] = ns; wnn[wrp] = nn; }
    __syncthreads();
    if (wrp == 0) {
        float m2 = (lid < 8) ? wmx[lid] : -INFINITY;
        float n2 = (lid < 8) ? wns[lid] : 0.0f;
        int   c2 = (lid < 8) ? wnn[lid] : 0;
#pragma unroll
        for (int o = 4; o > 0; o >>= 1) {
            m2 = fmaxf(m2, __shfl_xor_sync(0xFFFFFFFFu, m2, o));
            n2 += __shfl_xor_sync(0xFFFFFFFFu, n2, o);
            c2 += __shfl_xor_sync(0xFFFFFFFFu, c2, o);
        }
        if (lid == 0) { s_maxneg = m2; s_negsum = n2; s_nneg = c2; }
    }
    __syncthreads();

    const float maxneg = s_maxneg;

    float ps = 0.0f;
    int np = 0;
    uint32_t m = m_pc;
#pragma unroll
    for (int q = 0; q < 16; q++) {
        if (m & (1u << q)) {
            float sv = s[q];
            if ((sv - MARGIN) < maxneg) {
                np++;
                ps += __expf(-SCALE_POS * sv);
            }
        }
    }
#pragma unroll
    for (int o = 16; o > 0; o >>= 1) {
        ps += __shfl_xor_sync(0xFFFFFFFFu, ps, o);
        np += __shfl_xor_sync(0xFFFFFFFFu, np, o);
    }
    if (lid == 0) { wps[wrp] = ps; wnp[wrp] = np; }
    __syncthreads();
    if (tid == 0) {
        float pos_sum = 0.0f;
        int n_pos = 0;
#pragma unroll
        for (int w = 0; w < 8; w++) { pos_sum += wps[w]; n_pos += wnp[w]; }
        float neg_sum = s_negsum;
        int n_neg = s_nneg;
        float pos_loss = (1.0f / SCALE_POS) *
            __logf((pos_sum + __expf(-SCALE_POS * THRESH1)) / (float)(n_pos + 1));
        float neg_loss = (1.0f / SCALE_NEG) *
            __logf((neg_sum + __expf(SCALE_NEG * THRESH2)) / (float)(n_neg + 1));
        float per_row = __logf(5.33f + __expf(pos_loss + neg_loss));
        g_row[row] = (n_neg >= 1 && n_pos >= 1) ? per_row : 0.0f;
    }
}

// -------------------- kernel 4: final reduce (float4 + shuffle) --------------------
__global__ void __launch_bounds__(256) final_reduce_kernel(float* __restrict__ out) {
    __shared__ float wsum[8];
    int tid = threadIdx.x;
    int lid = tid & 31, wrp = tid >> 5;
    const float4* r4 = reinterpret_cast<const float4*>(g_row);
    float s = 0.0f;
#pragma unroll
    for (int it = 0; it < 4; it++) {
        float4 v = r4[it * 256 + tid];
        s += (v.x + v.y) + (v.z + v.w);
    }
#pragma unroll
    for (int o = 16; o > 0; o >>= 1) s += __shfl_xor_sync(0xFFFFFFFFu, s, o);
    if (lid == 0) wsum[wrp] = s;
    __syncthreads();
    if (tid == 0) {
        float t = 0.0f;
#pragma unroll
        for (int w = 0; w < 8; w++) t += wsum[w];
        out[0] = t * (1.0f / (float)NB);
    }
}

// ---------------------------------------------------------------------------
extern "C" void kernel_launch(void* const* d_in, const int* in_sizes, int n_in,
                              void* d_out, int out_size) {
    const float* feats = (const float*)d_in[0];
    const int* labels = (const int*)d_in[1];
    float* out = (float*)d_out;

    cudaFuncSetAttribute(gemm_mma_kernel,
                         cudaFuncAttributeMaxDynamicSharedMemorySize, DYNSMEM);

    labels_kernel<<<1, 256>>>(labels);
    convert_kernel<<<2048, 512>>>(feats);            // 4M elems, 1 float4/thread
    gemm_mma_kernel<<<dim3(32, 32), 128, DYNSMEM>>>();
    row_kernel<<<NB, 256>>>();
    final_reduce_kernel<<<1, 256>>>(out);
}

// round 14
// speedup vs baseline: 1.0354x; 1.0354x over previous
#include <cuda_runtime.h>
#include <cuda_fp16.h>
#include <math.h>
#include <stdint.h>

// Problem constants (fixed by the reference: B=4096, D=1024, N_CLASSES=64)
#define NB 4096
#define ND 1024

#define MARGIN    0.09f
#define SCALE_POS 2.0f
#define SCALE_NEG 40.0f
#define EPS_C     1e-5f
#define THRESH1   0.501f
#define THRESH2   0.531f

// -------------------- device scratch (no runtime allocation) --------------------
__device__ __half   g_sim16[(size_t)NB * NB];  // 32 MB similarity matrix (fp16)
__device__ float    g_t32[(size_t)NB * ND];    // 16 MB tf32-rounded feats
__device__ int      g_labels[NB];
__device__ uint32_t g_lab8[NB / 4];            // byte-packed labels (4 per word)
__device__ float    g_row[NB];

// -------------------- PTX helpers (plain sm_80 features only) --------------------
__device__ __forceinline__ uint32_t smem_u32(const void* p) {
    uint32_t a;
    asm("{ .reg .u64 t; cvta.to.shared.u64 t, %1; cvt.u32.u64 %0, t; }" : "=r"(a) : "l"(p));
    return a;
}
__device__ __forceinline__ void cp16(uint32_t s, const void* g) {
    asm volatile("cp.async.cg.shared.global [%0], [%1], 16;" :: "r"(s), "l"(g));
}
#define CP_COMMIT() asm volatile("cp.async.commit_group;" ::: "memory")
#define CP_WAIT2()  asm volatile("cp.async.wait_group 2;" ::: "memory")

__device__ __forceinline__ void ldsm4(uint32_t* r, uint32_t addr) {
    asm volatile("ldmatrix.sync.aligned.m8n8.x4.shared.b16 {%0,%1,%2,%3}, [%4];"
                 : "=r"(r[0]), "=r"(r[1]), "=r"(r[2]), "=r"(r[3]) : "r"(addr));
}
// m16n8k8 tf32: A = 4 regs, B = 2 regs, fp32 accum
__device__ __forceinline__ void mma_tf32(float* d, const uint32_t* a,
                                         uint32_t b0, uint32_t b1) {
    asm volatile(
        "mma.sync.aligned.m16n8k8.row.col.f32.tf32.tf32.f32 "
        "{%0,%1,%2,%3}, {%4,%5,%6,%7}, {%8,%9}, {%0,%1,%2,%3};"
        : "+f"(d[0]), "+f"(d[1]), "+f"(d[2]), "+f"(d[3])
        : "r"(a[0]), "r"(a[1]), "r"(a[2]), "r"(a[3]), "r"(b0), "r"(b1));
}
__device__ __forceinline__ uint32_t to_tf32(float x) {
    uint32_t o;
    asm("cvt.rna.tf32.f32 %0, %1;" : "=r"(o) : "f"(x));
    return o;
}

// -------------------- kernel 0: labels (int64/int32 auto-detect) + byte pack -------
__global__ void __launch_bounds__(256) labels_kernel(const int* __restrict__ lab) {
    __shared__ int sred[256];
    __shared__ int s_is64;
    int tid = threadIdx.x;
    int acc = 0;
    for (int i = tid; i < 2048; i += 256) acc |= lab[2 * i + 1];
    sred[tid] = acc;
    __syncthreads();
    for (int o = 128; o > 0; o >>= 1) {
        if (tid < o) sred[tid] |= sred[tid + o];
        __syncthreads();
    }
    if (tid == 0) s_is64 = (sred[0] == 0) ? 1 : 0;
    __syncthreads();
    int is64 = s_is64;
    for (int i = tid; i < NB; i += 256)
        g_labels[i] = is64 ? lab[2 * i] : lab[i];
    __syncthreads();
    for (int w = tid; w < NB / 4; w += 256) {
        uint32_t p = (uint32_t)(g_labels[4 * w] & 0xFF)
                   | ((uint32_t)(g_labels[4 * w + 1] & 0xFF) << 8)
                   | ((uint32_t)(g_labels[4 * w + 2] & 0xFF) << 16)
                   | ((uint32_t)(g_labels[4 * w + 3] & 0xFF) << 24);
        g_lab8[w] = p;
    }
}

// -------------------- kernel 1: f32 -> tf32 (round-to-nearest) --------------------
__global__ void __launch_bounds__(512) convert_kernel(const float* __restrict__ F) {
    size_t i = (size_t)blockIdx.x * 512 + threadIdx.x;   // one float4 per thread
    float4 v = reinterpret_cast<const float4*>(F)[i];
    uint4 o;
    o.x = to_tf32(v.x);
    o.y = to_tf32(v.y);
    o.z = to_tf32(v.z);
    o.w = to_tf32(v.w);
    reinterpret_cast<uint4*>(g_t32)[i] = o;
}

// -------------------- kernel 2: mma.sync tf32 symmetric GEMM (R12-proven) -----------
// sim = T * T^T single pass (tf32, K=1024). 128x128 tiles, upper triangle + mirror.
// 4 warps x (64x64); BK=32 f32; 3-stage cp.async pipeline; fp16 output stores.
#define STAGE_BYTES 32768          // A 16KB + B 16KB
#define NCHUNK 32
#define DYNSMEM (3 * STAGE_BYTES)  // 96 KB (epilogue reuses 64 KB of it)

__device__ __forceinline__ void load_chunk(int c, uint32_t stage,
                                           int rowA, int rowB, int tid) {
    const uint8_t* base = reinterpret_cast<const uint8_t*>(g_t32);
    size_t k0 = (size_t)c * 128;     // byte offset within 4096B row
    uint32_t sB = stage + 16384;
#pragma unroll
    for (int j = 0; j < 8; j++) {
        int u = (j << 7) + tid;          // 0..1023 16B units per operand
        int r = u >> 3;                  // row 0..127
        int ch = u & 7;                  // 16B chunk within 128B row
        uint32_t off = (uint32_t)((r << 7) + (ch << 4));
        uint32_t sw = off ^ ((off >> 3) & 0x70);
        cp16(stage + sw, base + (size_t)(rowA + r) * 4096 + k0 + (ch << 4));
        cp16(sB + sw,    base + (size_t)(rowB + r) * 4096 + k0 + (ch << 4));
    }
}

__global__ void __launch_bounds__(128, 2) gemm_mma_kernel() {
    extern __shared__ char dsm[];
    if ((int)blockIdx.x < (int)blockIdx.y) return;   // upper triangle only
    const int tid = threadIdx.x;
    const int lid = tid & 31;
    const int wid = tid >> 5;            // 0..3
    const int tileRow = blockIdx.y * 128;
    const int tileCol = blockIdx.x * 128;

    uint32_t SB = (smem_u32(dsm) + 127u) & ~127u;

    // warp tile: 64 (M) x 64 (N); warp grid 2 x 2
    const int mRow0 = (wid >> 1) * 64;
    const int nCol0 = (wid & 1) * 64;

    // ldmatrix lane addressing (b16-view of f32 tiles)
    const int aRow  = lid & 15;
    const int aKoff = ((lid >> 4) & 1) * 16;         // bytes
    const int bRow  = (lid & 7) + ((lid >> 4) << 3);
    const int bKoff = ((lid >> 3) & 1) * 16;         // bytes

    float acc[4][8][4];
#pragma unroll
    for (int mt = 0; mt < 4; mt++)
#pragma unroll
        for (int nt = 0; nt < 8; nt++)
#pragma unroll
            for (int q = 0; q < 4; q++) acc[mt][nt][q] = 0.0f;

    load_chunk(0, SB + 0 * STAGE_BYTES, tileRow, tileCol, tid); CP_COMMIT();
    load_chunk(1, SB + 1 * STAGE_BYTES, tileRow, tileCol, tid); CP_COMMIT();

    for (int c = 0; c < NCHUNK; c++) {
        if (c + 2 < NCHUNK)
            load_chunk(c + 2, SB + ((c + 2) % 3) * STAGE_BYTES, tileRow, tileCol, tid);
        CP_COMMIT();
        CP_WAIT2();
        __syncthreads();

        uint32_t sa = SB + (c % 3) * STAGE_BYTES;
        uint32_t sbm = sa + 16384;
#pragma unroll
        for (int kk = 0; kk < 4; kk++) {             // 4 x k8 within BK=32 f32
            uint32_t afrag[4][4];
#pragma unroll
            for (int mt = 0; mt < 4; mt++) {
                uint32_t off = (uint32_t)((mRow0 + mt * 16 + aRow) * 128 +
                                          aKoff + kk * 32);
                ldsm4(afrag[mt], sa + (off ^ ((off >> 3) & 0x70)));
            }
            uint32_t bfrag[4][4];                     // each g: n16 (two n8 frags)
#pragma unroll
            for (int g = 0; g < 4; g++) {
                uint32_t off = (uint32_t)((nCol0 + g * 16 + bRow) * 128 +
                                          bKoff + kk * 32);
                ldsm4(bfrag[g], sbm + (off ^ ((off >> 3) & 0x70)));
            }
#pragma unroll
            for (int mt = 0; mt < 4; mt++)
#pragma unroll
                for (int g = 0; g < 4; g++) {
                    mma_tf32(acc[mt][g * 2],     afrag[mt], bfrag[g][0], bfrag[g][1]);
                    mma_tf32(acc[mt][g * 2 + 1], afrag[mt], bfrag[g][2], bfrag[g][3]);
                }
        }
        __syncthreads();
    }

    // ---- epilogue: fragments -> XOR-swizzled SMEM -> fp16 normal + mirror stores ----
    float* C = reinterpret_cast<float*>(dsm);
#pragma unroll
    for (int mt = 0; mt < 4; mt++) {
        int r0 = mRow0 + mt * 16 + (lid >> 2);
#pragma unroll
        for (int nt = 0; nt < 8; nt++) {
            int cc = nCol0 + nt * 8 + (lid & 3) * 2;
            C[r0 * 128 + (cc ^ (r0 & 31))]       = acc[mt][nt][0];
            C[r0 * 128 + ((cc + 1) ^ (r0 & 31))] = acc[mt][nt][1];
            int r1 = r0 + 8;
            C[r1 * 128 + (cc ^ (r1 & 31))]       = acc[mt][nt][2];
            C[r1 * 128 + ((cc + 1) ^ (r1 & 31))] = acc[mt][nt][3];
        }
    }
    __syncthreads();

    // normal store: 8192 half2 units, 64 per thread
#pragma unroll 4
    for (int it = 0; it < 64; it++) {
        int idx = it * 128 + tid;
        int r = idx >> 6;                // 0..127
        int c2 = (idx & 63) * 2;         // even col
        float v0 = C[r * 128 + (c2 ^ (r & 31))];
        float v1 = C[r * 128 + ((c2 + 1) ^ (r & 31))];
        *reinterpret_cast<__half2*>(
            &g_sim16[(size_t)(tileRow + r) * NB + tileCol + c2]) =
            __floats2half2_rn(v0, v1);
    }
    if (blockIdx.x != blockIdx.y) {
#pragma unroll 4
        for (int it = 0; it < 64; it++) {
            int idx = it * 128 + tid;
            int j = idx >> 6;            // mirror row offset 0..127
            int i2 = (idx & 63) * 2;     // even mirror col
            float v0 = C[i2 * 128 + (j ^ (i2 & 31))];
            float v1 = C[(i2 + 1) * 128 + (j ^ ((i2 + 1) & 31))];
            *reinterpret_cast<__half2*>(
                &g_sim16[(size_t)(tileCol + j) * NB + tileRow + i2]) =
                __floats2half2_rn(v0, v1);
        }
    }
}

// -------------------- kernel 3: per-row reductions (fp16 sim, byte labels) ----------
__global__ void __launch_bounds__(256) row_kernel() {
    const int row = blockIdx.x;
    const int tid = threadIdx.x;
    const int lid = tid & 31;
    const int wrp = tid >> 5;

    __shared__ float wmx[8], wns[8], wps[8];
    __shared__ int   wnn[8], wnp[8];
    __shared__ float s_maxneg, s_negsum;
    __shared__ int   s_nneg;

    const uint4* srow = reinterpret_cast<const uint4*>(g_sim16 + (size_t)row * NB);
    const uint2* lab2 = reinterpret_cast<const uint2*>(g_lab8);
    const int rl = g_labels[row];
    const uint32_t rl4 = (uint32_t)(rl & 0xFF) * 0x01010101u;

    float s[16];
    uint32_t m_pc = 0;   // bit q: label == rl && s < 1-eps (pos candidate)

    float mx = -INFINITY, ns = 0.0f;
    int nn = 0;

#pragma unroll
    for (int it = 0; it < 2; it++) {
        uint4 raw = srow[it * 256 + tid];            // 8 halves
        uint2 lw = lab2[it * 256 + tid];             // 8 byte-labels
        uint32_t eq0 = __vcmpeq4(lw.x, rl4);         // 0xFF per matching byte
        uint32_t eq1 = __vcmpeq4(lw.y, rl4);
        nn += __popc(~eq0 & 0x01010101u) + __popc(~eq1 & 0x01010101u);
        float2 f0 = __half22float2(*reinterpret_cast<const __half2*>(&raw.x));
        float2 f1 = __half22float2(*reinterpret_cast<const __half2*>(&raw.y));
        float2 f2 = __half22float2(*reinterpret_cast<const __half2*>(&raw.z));
        float2 f3 = __half22float2(*reinterpret_cast<const __half2*>(&raw.w));
        float sv[8] = {f0.x, f0.y, f1.x, f1.y, f2.x, f2.y, f3.x, f3.y};
#pragma unroll
        for (int q = 0; q < 8; q++) {
            s[it * 8 + q] = sv[q];
            uint32_t eqw = (q < 4) ? eq0 : eq1;
            bool iseq = (eqw >> ((q & 3) * 8)) & 1;
            if (!iseq) {
                ns += __expf(SCALE_NEG * sv[q]);
                mx = fmaxf(mx, sv[q]);
            } else if (sv[q] < (1.0f - EPS_C)) {
                m_pc |= (1u << (it * 8 + q));
            }
        }
    }

#pragma unroll
    for (int o = 16; o > 0; o >>= 1) {
        mx = fmaxf(mx, __shfl_xor_sync(0xFFFFFFFFu, mx, o));
        ns += __shfl_xor_sync(0xFFFFFFFFu, ns, o);
        nn += __shfl_xor_sync(0xFFFFFFFFu, nn, o);
    }
    if (lid == 0) { wmx[wrp] = mx; wns[wrp] = ns; wnn[wrp] = nn; }
    __syncthreads();
    if (wrp == 0) {
        float m2 = (lid < 8) ? wmx[lid] : -INFINITY;
        float n2 = (lid < 8) ? wns[lid] : 0.0f;
        int   c2 = (lid < 8) ? wnn[lid] : 0;
#pragma unroll
        for (int o = 4; o > 0; o >>= 1) {
            m2 = fmaxf(m2, __shfl_xor_sync(0xFFFFFFFFu, m2, o));
            n2 += __shfl_xor_sync(0xFFFFFFFFu, n2, o);
            c2 += __shfl_xor_sync(0xFFFFFFFFu, c2, o);
        }
        if (lid == 0) { s_maxneg = m2; s_negsum = n2; s_nneg = c2; }
    }
    __syncthreads();

    const float maxneg = s_maxneg;

    float ps = 0.0f;
    int np = 0;
    uint32_t m = m_pc;
#pragma unroll
    for (int q = 0; q < 16; q++) {
        if (m & (1u << q)) {
            float sv = s[q];
            if ((sv - MARGIN) < maxneg) {
                np++;
                ps += __expf(-SCALE_POS * sv);
            }
        }
    }
#pragma unroll
    for (int o = 16; o > 0; o >>= 1) {
        ps += __shfl_xor_sync(0xFFFFFFFFu, ps, o);
        np += __shfl_xor_sync(0xFFFFFFFFu, np, o);
    }
    if (lid == 0) { wps[wrp] = ps; wnp[wrp] = np; }
    __syncthreads();
    if (tid == 0) {
        float pos_sum = 0.0f;
        int n_pos = 0;
#pragma unroll
        for (int w = 0; w < 8; w++) { pos_sum += wps[w]; n_pos += wnp[w]; }
        float neg_sum = s_negsum;
        int n_neg = s_nneg;
        float pos_loss = (1.0f / SCALE_POS) *
            __logf((pos_sum + __expf(-SCALE_POS * THRESH1)) / (float)(n_pos + 1));
        float neg_loss = (1.0f / SCALE_NEG) *
            __logf((neg_sum + __expf(SCALE_NEG * THRESH2)) / (float)(n_neg + 1));
        float per_row = __logf(5.33f + __expf(pos_loss + neg_loss));
        g_row[row] = (n_neg >= 1 && n_pos >= 1) ? per_row : 0.0f;
    }
}

// -------------------- kernel 4: final reduce (float4 + shuffle) --------------------
__global__ void __launch_bounds__(256) final_reduce_kernel(float* __restrict__ out) {
    __shared__ float wsum[8];
    int tid = threadIdx.x;
    int lid = tid & 31, wrp = tid >> 5;
    const float4* r4 = reinterpret_cast<const float4*>(g_row);
    float s = 0.0f;
#pragma unroll
    for (int it = 0; it < 4; it++) {
        float4 v = r4[it * 256 + tid];
        s += (v.x + v.y) + (v.z + v.w);
    }
#pragma unroll
    for (int o = 16; o > 0; o >>= 1) s += __shfl_xor_sync(0xFFFFFFFFu, s, o);
    if (lid == 0) wsum[wrp] = s;
    __syncthreads();
    if (tid == 0) {
        float t = 0.0f;
#pragma unroll
        for (int w = 0; w < 8; w++) t += wsum[w];
        out[0] = t * (1.0f / (float)NB);
    }
}

// ---------------------------------------------------------------------------
extern "C" void kernel_launch(void* const* d_in, const int* in_sizes, int n_in,
                              void* d_out, int out_size) {
    const float* feats = (const float*)d_in[0];
    const int* labels = (const int*)d_in[1];
    float* out = (float*)d_out;

    cudaFuncSetAttribute(gemm_mma_kernel,
                         cudaFuncAttributeMaxDynamicSharedMemorySize, DYNSMEM);

    labels_kernel<<<1, 256>>>(labels);
    convert_kernel<<<2048, 512>>>(feats);            // 4M elems, 1 float4/thread
    gemm_mma_kernel<<<dim3(32, 32), 128, DYNSMEM>>>();
    row_kernel<<<NB, 256>>>();
    final_reduce_kernel<<<1, 256>>>(out);
}

// round 15
// speedup vs baseline: 1.0455x; 1.0098x over previous
#include <cuda_runtime.h>
#include <cuda_fp16.h>
#include <math.h>
#include <stdint.h>

// Problem constants (fixed by the reference: B=4096, D=1024, N_CLASSES=64)
#define NB 4096
#define ND 1024

#define MARGIN    0.09f
#define SCALE_POS 2.0f
#define SCALE_NEG 40.0f
#define EPS_C     1e-5f
#define THRESH1   0.501f
#define THRESH2   0.531f

// -------------------- device scratch (no runtime allocation) --------------------
__device__ __half   g_sim16[(size_t)NB * NB];  // 32 MB similarity matrix (fp16)
__device__ float    g_t32[(size_t)NB * ND];    // 16 MB tf32-rounded feats
__device__ int      g_labels[NB];
__device__ uint32_t g_lab8[NB / 4];            // byte-packed labels (4 per word)
__device__ float    g_row[NB];
__device__ int      g_ticket;                  // last-block ticket (self-resetting)

// -------------------- PTX helpers (plain sm_80 features only) --------------------
__device__ __forceinline__ uint32_t smem_u32(const void* p) {
    uint32_t a;
    asm("{ .reg .u64 t; cvta.to.shared.u64 t, %1; cvt.u32.u64 %0, t; }" : "=r"(a) : "l"(p));
    return a;
}
__device__ __forceinline__ void cp16(uint32_t s, const void* g) {
    asm volatile("cp.async.cg.shared.global [%0], [%1], 16;" :: "r"(s), "l"(g));
}
#define CP_COMMIT() asm volatile("cp.async.commit_group;" ::: "memory")
#define CP_WAIT2()  asm volatile("cp.async.wait_group 2;" ::: "memory")

__device__ __forceinline__ void ldsm4(uint32_t* r, uint32_t addr) {
    asm volatile("ldmatrix.sync.aligned.m8n8.x4.shared.b16 {%0,%1,%2,%3}, [%4];"
                 : "=r"(r[0]), "=r"(r[1]), "=r"(r[2]), "=r"(r[3]) : "r"(addr));
}
// m16n8k8 tf32: A = 4 regs, B = 2 regs, fp32 accum
__device__ __forceinline__ void mma_tf32(float* d, const uint32_t* a,
                                         uint32_t b0, uint32_t b1) {
    asm volatile(
        "mma.sync.aligned.m16n8k8.row.col.f32.tf32.tf32.f32 "
        "{%0,%1,%2,%3}, {%4,%5,%6,%7}, {%8,%9}, {%0,%1,%2,%3};"
        : "+f"(d[0]), "+f"(d[1]), "+f"(d[2]), "+f"(d[3])
        : "r"(a[0]), "r"(a[1]), "r"(a[2]), "r"(a[3]), "r"(b0), "r"(b1));
}
__device__ __forceinline__ uint32_t to_tf32(float x) {
    uint32_t o;
    asm("cvt.rna.tf32.f32 %0, %1;" : "=r"(o) : "f"(x));
    return o;
}

// -------------------- kernel 1: convert + (block 2048) labels --------------------
// blocks 0..2047: f32 -> tf32 round-to-nearest (one float4 per thread)
// block 2048:     label dtype auto-detect (int64 vs int32), normalize, byte-pack
__global__ void __launch_bounds__(512) convert_kernel(const float* __restrict__ F,
                                                      const int* __restrict__ lab) {
    if (blockIdx.x < 2048) {
        size_t i = (size_t)blockIdx.x * 512 + threadIdx.x;
        float4 v = reinterpret_cast<const float4*>(F)[i];
        uint4 o;
        o.x = to_tf32(v.x);
        o.y = to_tf32(v.y);
        o.z = to_tf32(v.z);
        o.w = to_tf32(v.w);
        reinterpret_cast<uint4*>(g_t32)[i] = o;
        return;
    }
    // ---- labels block ----
    __shared__ int sred[512];
    __shared__ int s_is64;
    int tid = threadIdx.x;
    int acc = 0;
    for (int i = tid; i < 2048; i += 512) acc |= lab[2 * i + 1];
    sred[tid] = acc;
    __syncthreads();
    for (int o = 256; o > 0; o >>= 1) {
        if (tid < o) sred[tid] |= sred[tid + o];
        __syncthreads();
    }
    if (tid == 0) s_is64 = (sred[0] == 0) ? 1 : 0;
    __syncthreads();
    int is64 = s_is64;
    for (int i = tid; i < NB; i += 512)
        g_labels[i] = is64 ? lab[2 * i] : lab[i];
    __syncthreads();
    for (int w = tid; w < NB / 4; w += 512) {
        uint32_t p = (uint32_t)(g_labels[4 * w] & 0xFF)
                   | ((uint32_t)(g_labels[4 * w + 1] & 0xFF) << 8)
                   | ((uint32_t)(g_labels[4 * w + 2] & 0xFF) << 16)
                   | ((uint32_t)(g_labels[4 * w + 3] & 0xFF) << 24);
        g_lab8[w] = p;
    }
}

// -------------------- kernel 2: mma.sync tf32 symmetric GEMM (R12-proven) -----------
// sim = T * T^T single pass (tf32, K=1024). 128x128 tiles, upper triangle + mirror.
// 4 warps x (64x64); BK=32 f32; 3-stage cp.async pipeline; fp16 output stores.
#define STAGE_BYTES 32768          // A 16KB + B 16KB
#define NCHUNK 32
#define DYNSMEM (3 * STAGE_BYTES)  // 96 KB (epilogue reuses 64 KB of it)

__device__ __forceinline__ void load_chunk(int c, uint32_t stage,
                                           int rowA, int rowB, int tid) {
    const uint8_t* base = reinterpret_cast<const uint8_t*>(g_t32);
    size_t k0 = (size_t)c * 128;     // byte offset within 4096B row
    uint32_t sB = stage + 16384;
#pragma unroll
    for (int j = 0; j < 8; j++) {
        int u = (j << 7) + tid;          // 0..1023 16B units per operand
        int r = u >> 3;                  // row 0..127
        int ch = u & 7;                  // 16B chunk within 128B row
        uint32_t off = (uint32_t)((r << 7) + (ch << 4));
        uint32_t sw = off ^ ((off >> 3) & 0x70);
        cp16(stage + sw, base + (size_t)(rowA + r) * 4096 + k0 + (ch << 4));
        cp16(sB + sw,    base + (size_t)(rowB + r) * 4096 + k0 + (ch << 4));
    }
}

__global__ void __launch_bounds__(128, 2) gemm_mma_kernel() {
    extern __shared__ char dsm[];
    if ((int)blockIdx.x < (int)blockIdx.y) return;   // upper triangle only
    const int tid = threadIdx.x;
    const int lid = tid & 31;
    const int wid = tid >> 5;            // 0..3
    const int tileRow = blockIdx.y * 128;
    const int tileCol = blockIdx.x * 128;

    uint32_t SB = (smem_u32(dsm) + 127u) & ~127u;

    // warp tile: 64 (M) x 64 (N); warp grid 2 x 2
    const int mRow0 = (wid >> 1) * 64;
    const int nCol0 = (wid & 1) * 64;

    // ldmatrix lane addressing (b16-view of f32 tiles)
    const int aRow  = lid & 15;
    const int aKoff = ((lid >> 4) & 1) * 16;         // bytes
    const int bRow  = (lid & 7) + ((lid >> 4) << 3);
    const int bKoff = ((lid >> 3) & 1) * 16;         // bytes

    float acc[4][8][4];
#pragma unroll
    for (int mt = 0; mt < 4; mt++)
#pragma unroll
        for (int nt = 0; nt < 8; nt++)
#pragma unroll
            for (int q = 0; q < 4; q++) acc[mt][nt][q] = 0.0f;

    load_chunk(0, SB + 0 * STAGE_BYTES, tileRow, tileCol, tid); CP_COMMIT();
    load_chunk(1, SB + 1 * STAGE_BYTES, tileRow, tileCol, tid); CP_COMMIT();

    for (int c = 0; c < NCHUNK; c++) {
        if (c + 2 < NCHUNK)
            load_chunk(c + 2, SB + ((c + 2) % 3) * STAGE_BYTES, tileRow, tileCol, tid);
        CP_COMMIT();
        CP_WAIT2();
        __syncthreads();

        uint32_t sa = SB + (c % 3) * STAGE_BYTES;
        uint32_t sbm = sa + 16384;
#pragma unroll
        for (int kk = 0; kk < 4; kk++) {             // 4 x k8 within BK=32 f32
            uint32_t afrag[4][4];
#pragma unroll
            for (int mt = 0; mt < 4; mt++) {
                uint32_t off = (uint32_t)((mRow0 + mt * 16 + aRow) * 128 +
                                          aKoff + kk * 32);
                ldsm4(afrag[mt], sa + (off ^ ((off >> 3) & 0x70)));
            }
            uint32_t bfrag[4][4];                     // each g: n16 (two n8 frags)
#pragma unroll
            for (int g = 0; g < 4; g++) {
                uint32_t off = (uint32_t)((nCol0 + g * 16 + bRow) * 128 +
                                          bKoff + kk * 32);
                ldsm4(bfrag[g], sbm + (off ^ ((off >> 3) & 0x70)));
            }
#pragma unroll
            for (int mt = 0; mt < 4; mt++)
#pragma unroll
                for (int g = 0; g < 4; g++) {
                    mma_tf32(acc[mt][g * 2],     afrag[mt], bfrag[g][0], bfrag[g][1]);
                    mma_tf32(acc[mt][g * 2 + 1], afrag[mt], bfrag[g][2], bfrag[g][3]);
                }
        }
        __syncthreads();
    }

    // ---- epilogue: fragments -> XOR-swizzled SMEM -> fp16 normal + mirror stores ----
    float* C = reinterpret_cast<float*>(dsm);
#pragma unroll
    for (int mt = 0; mt < 4; mt++) {
        int r0 = mRow0 + mt * 16 + (lid >> 2);
#pragma unroll
        for (int nt = 0; nt < 8; nt++) {
            int cc = nCol0 + nt * 8 + (lid & 3) * 2;
            C[r0 * 128 + (cc ^ (r0 & 31))]       = acc[mt][nt][0];
            C[r0 * 128 + ((cc + 1) ^ (r0 & 31))] = acc[mt][nt][1];
            int r1 = r0 + 8;
            C[r1 * 128 + (cc ^ (r1 & 31))]       = acc[mt][nt][2];
            C[r1 * 128 + ((cc + 1) ^ (r1 & 31))] = acc[mt][nt][3];
        }
    }
    __syncthreads();

    // normal store: 8192 half2 units, 64 per thread
#pragma unroll 4
    for (int it = 0; it < 64; it++) {
        int idx = it * 128 + tid;
        int r = idx >> 6;                // 0..127
        int c2 = (idx & 63) * 2;         // even col
        float v0 = C[r * 128 + (c2 ^ (r & 31))];
        float v1 = C[r * 128 + ((c2 + 1) ^ (r & 31))];
        *reinterpret_cast<__half2*>(
            &g_sim16[(size_t)(tileRow + r) * NB + tileCol + c2]) =
            __floats2half2_rn(v0, v1);
    }
    if (blockIdx.x != blockIdx.y) {
#pragma unroll 4
        for (int it = 0; it < 64; it++) {
            int idx = it * 128 + tid;
            int j = idx >> 6;            // mirror row offset 0..127
            int i2 = (idx & 63) * 2;     // even mirror col
            float v0 = C[i2 * 128 + (j ^ (i2 & 31))];
            float v1 = C[(i2 + 1) * 128 + (j ^ ((i2 + 1) & 31))];
            *reinterpret_cast<__half2*>(
                &g_sim16[(size_t)(tileCol + j) * NB + tileRow + i2]) =
                __floats2half2_rn(v0, v1);
        }
    }
}

// -------------------- kernel 3: per-row reductions + fused final reduce -------------
__global__ void __launch_bounds__(256) row_kernel(float* __restrict__ out) {
    const int row = blockIdx.x;
    const int tid = threadIdx.x;
    const int lid = tid & 31;
    const int wrp = tid >> 5;

    __shared__ float wmx[8], wns[8], wps[8];
    __shared__ int   wnn[8], wnp[8];
    __shared__ float s_maxneg, s_negsum;
    __shared__ int   s_nneg;
    __shared__ int   s_last;

    const uint4* srow = reinterpret_cast<const uint4*>(g_sim16 + (size_t)row * NB);
    const uint2* lab2 = reinterpret_cast<const uint2*>(g_lab8);
    const int rl = g_labels[row];
    const uint32_t rl4 = (uint32_t)(rl & 0xFF) * 0x01010101u;

    float s[16];
    uint32_t m_pc = 0;   // bit q: label == rl && s < 1-eps (pos candidate)

    float mx = -INFINITY, ns = 0.0f;
    int nn = 0;

#pragma unroll
    for (int it = 0; it < 2; it++) {
        uint4 raw = srow[it * 256 + tid];            // 8 halves
        uint2 lw = lab2[it * 256 + tid];             // 8 byte-labels
        uint32_t eq0 = __vcmpeq4(lw.x, rl4);         // 0xFF per matching byte
        uint32_t eq1 = __vcmpeq4(lw.y, rl4);
        nn += __popc(~eq0 & 0x01010101u) + __popc(~eq1 & 0x01010101u);
        float2 f0 = __half22float2(*reinterpret_cast<const __half2*>(&raw.x));
        float2 f1 = __half22float2(*reinterpret_cast<const __half2*>(&raw.y));
        float2 f2 = __half22float2(*reinterpret_cast<const __half2*>(&raw.z));
        float2 f3 = __half22float2(*reinterpret_cast<const __half2*>(&raw.w));
        float sv[8] = {f0.x, f0.y, f1.x, f1.y, f2.x, f2.y, f3.x, f3.y};
#pragma unroll
        for (int q = 0; q < 8; q++) {
            s[it * 8 + q] = sv[q];
            uint32_t eqw = (q < 4) ? eq0 : eq1;
            bool iseq = (eqw >> ((q & 3) * 8)) & 1;
            if (!iseq) {
                ns += __expf(SCALE_NEG * sv[q]);
                mx = fmaxf(mx, sv[q]);
            } else if (sv[q] < (1.0f - EPS_C)) {
                m_pc |= (1u << (it * 8 + q));
            }
        }
    }

#pragma unroll
    for (int o = 16; o > 0; o >>= 1) {
        mx = fmaxf(mx, __shfl_xor_sync(0xFFFFFFFFu, mx, o));
        ns += __shfl_xor_sync(0xFFFFFFFFu, ns, o);
        nn += __shfl_xor_sync(0xFFFFFFFFu, nn, o);
    }
    if (lid == 0) { wmx[wrp] = mx; wns[wrp] = ns; wnn[wrp] = nn; }
    __syncthreads();
    if (wrp == 0) {
        float m2 = (lid < 8) ? wmx[lid] : -INFINITY;
        float n2 = (lid < 8) ? wns[lid] : 0.0f;
        int   c2 = (lid < 8) ? wnn[lid] : 0;
#pragma unroll
        for (int o = 4; o > 0; o >>= 1) {
            m2 = fmaxf(m2, __shfl_xor_sync(0xFFFFFFFFu, m2, o));
            n2 += __shfl_xor_sync(0xFFFFFFFFu, n2, o);
            c2 += __shfl_xor_sync(0xFFFFFFFFu, c2, o);
        }
        if (lid == 0) { s_maxneg = m2; s_negsum = n2; s_nneg = c2; }
    }
    __syncthreads();

    const float maxneg = s_maxneg;

    float ps = 0.0f;
    int np = 0;
    uint32_t m = m_pc;
#pragma unroll
    for (int q = 0; q < 16; q++) {
        if (m & (1u << q)) {
            float sv = s[q];
            if ((sv - MARGIN) < maxneg) {
                np++;
                ps += __expf(-SCALE_POS * sv);
            }
        }
    }
#pragma unroll
    for (int o = 16; o > 0; o >>= 1) {
        ps += __shfl_xor_sync(0xFFFFFFFFu, ps, o);
        np += __shfl_xor_sync(0xFFFFFFFFu, np, o);
    }
    if (lid == 0) { wps[wrp] = ps; wnp[wrp] = np; }
    __syncthreads();
    if (tid == 0) {
        float pos_sum = 0.0f;
        int n_pos = 0;
#pragma unroll
        for (int w = 0; w < 8; w++) { pos_sum += wps[w]; n_pos += wnp[w]; }
        float neg_sum = s_negsum;
        int n_neg = s_nneg;
        float pos_loss = (1.0f / SCALE_POS) *
            __logf((pos_sum + __expf(-SCALE_POS * THRESH1)) / (float)(n_pos + 1));
        float neg_loss = (1.0f / SCALE_NEG) *
            __logf((neg_sum + __expf(SCALE_NEG * THRESH2)) / (float)(n_neg + 1));
        float per_row = __logf(5.33f + __expf(pos_loss + neg_loss));
        g_row[row] = (n_neg >= 1 && n_pos >= 1) ? per_row : 0.0f;
        __threadfence();
        int t = atomicAdd(&g_ticket, 1);
        s_last = (t == NB - 1) ? 1 : 0;
    }
    __syncthreads();

    // last CTA to finish: deterministic fixed-order final reduction
    if (s_last) {
        __shared__ float wsum[8];
        const float4* r4 = reinterpret_cast<const float4*>(g_row);
        float acc4 = 0.0f;
#pragma unroll
        for (int it = 0; it < 4; it++) {
            float4 v = r4[it * 256 + tid];
            acc4 += (v.x + v.y) + (v.z + v.w);
        }
#pragma unroll
        for (int o = 16; o > 0; o >>= 1)
            acc4 += __shfl_xor_sync(0xFFFFFFFFu, acc4, o);
        if (lid == 0) wsum[wrp] = acc4;
        __syncthreads();
        if (tid == 0) {
            float t = 0.0f;
#pragma unroll
            for (int w = 0; w < 8; w++) t += wsum[w];
            out[0] = t * (1.0f / (float)NB);
            g_ticket = 0;                 // reset for next graph replay
        }
    }
}

// ---------------------------------------------------------------------------
extern "C" void kernel_launch(void* const* d_in, const int* in_sizes, int n_in,
                              void* d_out, int out_size) {
    const float* feats = (const float*)d_in[0];
    const int* labels = (const int*)d_in[1];
    float* out = (float*)d_out;

    cudaFuncSetAttribute(gemm_mma_kernel,
                         cudaFuncAttributeMaxDynamicSharedMemorySize, DYNSMEM);

    convert_kernel<<<2049, 512>>>(feats, labels);    // tf32 convert + labels
    gemm_mma_kernel<<<dim3(32, 32), 128, DYNSMEM>>>();
    row_kernel<<<NB, 256>>>(out);
}

// round 16
// speedup vs baseline: 1.0654x; 1.0190x over previous
#include <cuda_runtime.h>
#include <cuda_fp16.h>
#include <math.h>
#include <stdint.h>

// Problem constants (fixed by the reference: B=4096, D=1024, N_CLASSES=64)
#define NB 4096
#define ND 1024

#define MARGIN    0.09f
#define SCALE_POS 2.0f
#define SCALE_NEG 40.0f
#define EPS_C     1e-5f
#define THRESH1   0.501f
#define THRESH2   0.531f

// -------------------- device scratch (no runtime allocation) --------------------
__device__ __half   g_sim16[(size_t)NB * NB];  // 32 MB similarity matrix (fp16)
__device__ int      g_labels[NB];
__device__ uint32_t g_lab8[NB / 4];            // byte-packed labels (4 per word)
__device__ float    g_row[NB];
__device__ int      g_ticket;                  // last-block ticket (self-resetting)

// -------------------- PTX helpers (plain sm_80 features only) --------------------
__device__ __forceinline__ uint32_t smem_u32(const void* p) {
    uint32_t a;
    asm("{ .reg .u64 t; cvta.to.shared.u64 t, %1; cvt.u32.u64 %0, t; }" : "=r"(a) : "l"(p));
    return a;
}
__device__ __forceinline__ void cp16(uint32_t s, const void* g) {
    asm volatile("cp.async.cg.shared.global [%0], [%1], 16;" :: "r"(s), "l"(g));
}
#define CP_COMMIT() asm volatile("cp.async.commit_group;" ::: "memory")
#define CP_WAIT2()  asm volatile("cp.async.wait_group 2;" ::: "memory")

__device__ __forceinline__ void ldsm4(uint32_t* r, uint32_t addr) {
    asm volatile("ldmatrix.sync.aligned.m8n8.x4.shared.b16 {%0,%1,%2,%3}, [%4];"
                 : "=r"(r[0]), "=r"(r[1]), "=r"(r[2]), "=r"(r[3]) : "r"(addr));
}
// m16n8k8 tf32: A = 4 regs, B = 2 regs, fp32 accum.
// Operands carry RAW fp32 bits -> hardware truncates to tf32 (error analyzed OK).
__device__ __forceinline__ void mma_tf32(float* d, const uint32_t* a,
                                         uint32_t b0, uint32_t b1) {
    asm volatile(
        "mma.sync.aligned.m16n8k8.row.col.f32.tf32.tf32.f32 "
        "{%0,%1,%2,%3}, {%4,%5,%6,%7}, {%8,%9}, {%0,%1,%2,%3};"
        : "+f"(d[0]), "+f"(d[1]), "+f"(d[2]), "+f"(d[3])
        : "r"(a[0]), "r"(a[1]), "r"(a[2]), "r"(a[3]), "r"(b0), "r"(b1));
}

// -------------------- kernel 0: labels (int64/int32 auto-detect) + byte pack -------
__global__ void __launch_bounds__(256) labels_kernel(const int* __restrict__ lab) {
    __shared__ int sred[256];
    __shared__ int s_is64;
    int tid = threadIdx.x;
    int acc = 0;
    for (int i = tid; i < 2048; i += 256) acc |= lab[2 * i + 1];
    sred[tid] = acc;
    __syncthreads();
    for (int o = 128; o > 0; o >>= 1) {
        if (tid < o) sred[tid] |= sred[tid + o];
        __syncthreads();
    }
    if (tid == 0) s_is64 = (sred[0] == 0) ? 1 : 0;
    __syncthreads();
    int is64 = s_is64;
    for (int i = tid; i < NB; i += 256)
        g_labels[i] = is64 ? lab[2 * i] : lab[i];
    __syncthreads();
    for (int w = tid; w < NB / 4; w += 256) {
        uint32_t p = (uint32_t)(g_labels[4 * w] & 0xFF)
                   | ((uint32_t)(g_labels[4 * w + 1] & 0xFF) << 8)
                   | ((uint32_t)(g_labels[4 * w + 2] & 0xFF) << 16)
                   | ((uint32_t)(g_labels[4 * w + 3] & 0xFF) << 24);
        g_lab8[w] = p;
    }
}

// -------------------- kernel 1: mma.sync tf32 symmetric GEMM --------------------
// sim = F * F^T single pass, reading feats (raw fp32 -> tf32 truncation) directly.
// 128x128 tiles, upper triangle + mirror; 4 warps x (64x64); BK=32 f32;
// 3-stage cp.async pipeline; fp16 output stores.
#define STAGE_BYTES 32768          // A 16KB + B 16KB
#define NCHUNK 32
#define DYNSMEM (3 * STAGE_BYTES)  // 96 KB (epilogue reuses 64 KB of it)

__device__ __forceinline__ void load_chunk(const uint8_t* base, int c, uint32_t stage,
                                           int rowA, int rowB, int tid) {
    size_t k0 = (size_t)c * 128;     // byte offset within 4096B row
    uint32_t sB = stage + 16384;
#pragma unroll
    for (int j = 0; j < 8; j++) {
        int u = (j << 7) + tid;          // 0..1023 16B units per operand
        int r = u >> 3;                  // row 0..127
        int ch = u & 7;                  // 16B chunk within 128B row
        uint32_t off = (uint32_t)((r << 7) + (ch << 4));
        uint32_t sw = off ^ ((off >> 3) & 0x70);
        cp16(stage + sw, base + (size_t)(rowA + r) * 4096 + k0 + (ch << 4));
        cp16(sB + sw,    base + (size_t)(rowB + r) * 4096 + k0 + (ch << 4));
    }
}

__global__ void __launch_bounds__(128, 2) gemm_mma_kernel(const float* __restrict__ feats) {
    extern __shared__ char dsm[];
    if ((int)blockIdx.x < (int)blockIdx.y) return;   // upper triangle only
    const uint8_t* base = reinterpret_cast<const uint8_t*>(feats);
    const int tid = threadIdx.x;
    const int lid = tid & 31;
    const int wid = tid >> 5;            // 0..3
    const int tileRow = blockIdx.y * 128;
    const int tileCol = blockIdx.x * 128;

    uint32_t SB = (smem_u32(dsm) + 127u) & ~127u;

    // warp tile: 64 (M) x 64 (N); warp grid 2 x 2
    const int mRow0 = (wid >> 1) * 64;
    const int nCol0 = (wid & 1) * 64;

    // ldmatrix lane addressing (b16-view of f32 tiles)
    const int aRow  = lid & 15;
    const int aKoff = ((lid >> 4) & 1) * 16;         // bytes
    const int bRow  = (lid & 7) + ((lid >> 4) << 3);
    const int bKoff = ((lid >> 3) & 1) * 16;         // bytes

    float acc[4][8][4];
#pragma unroll
    for (int mt = 0; mt < 4; mt++)
#pragma unroll
        for (int nt = 0; nt < 8; nt++)
#pragma unroll
            for (int q = 0; q < 4; q++) acc[mt][nt][q] = 0.0f;

    load_chunk(base, 0, SB + 0 * STAGE_BYTES, tileRow, tileCol, tid); CP_COMMIT();
    load_chunk(base, 1, SB + 1 * STAGE_BYTES, tileRow, tileCol, tid); CP_COMMIT();

    for (int c = 0; c < NCHUNK; c++) {
        if (c + 2 < NCHUNK)
            load_chunk(base, c + 2, SB + ((c + 2) % 3) * STAGE_BYTES,
                       tileRow, tileCol, tid);
        CP_COMMIT();
        CP_WAIT2();
        __syncthreads();

        uint32_t sa = SB + (c % 3) * STAGE_BYTES;
        uint32_t sbm = sa + 16384;
#pragma unroll
        for (int kk = 0; kk < 4; kk++) {             // 4 x k8 within BK=32 f32
            uint32_t afrag[4][4];
#pragma unroll
            for (int mt = 0; mt < 4; mt++) {
                uint32_t off = (uint32_t)((mRow0 + mt * 16 + aRow) * 128 +
                                          aKoff + kk * 32);
                ldsm4(afrag[mt], sa + (off ^ ((off >> 3) & 0x70)));
            }
            uint32_t bfrag[4][4];                     // each g: n16 (two n8 frags)
#pragma unroll
            for (int g = 0; g < 4; g++) {
                uint32_t off = (uint32_t)((nCol0 + g * 16 + bRow) * 128 +
                                          bKoff + kk * 32);
                ldsm4(bfrag[g], sbm + (off ^ ((off >> 3) & 0x70)));
            }
#pragma unroll
            for (int mt = 0; mt < 4; mt++)
#pragma unroll
                for (int g = 0; g < 4; g++) {
                    mma_tf32(acc[mt][g * 2],     afrag[mt], bfrag[g][0], bfrag[g][1]);
                    mma_tf32(acc[mt][g * 2 + 1], afrag[mt], bfrag[g][2], bfrag[g][3]);
                }
        }
        __syncthreads();
    }

    // ---- epilogue: fragments -> XOR-swizzled SMEM -> fp16 normal + mirror stores ----
    float* C = reinterpret_cast<float*>(dsm);
#pragma unroll
    for (int mt = 0; mt < 4; mt++) {
        int r0 = mRow0 + mt * 16 + (lid >> 2);
#pragma unroll
        for (int nt = 0; nt < 8; nt++) {
            int cc = nCol0 + nt * 8 + (lid & 3) * 2;
            C[r0 * 128 + (cc ^ (r0 & 31))]       = acc[mt][nt][0];
            C[r0 * 128 + ((cc + 1) ^ (r0 & 31))] = acc[mt][nt][1];
            int r1 = r0 + 8;
            C[r1 * 128 + (cc ^ (r1 & 31))]       = acc[mt][nt][2];
            C[r1 * 128 + ((cc + 1) ^ (r1 & 31))] = acc[mt][nt][3];
        }
    }
    __syncthreads();

    // normal store: 8192 half2 units, 64 per thread
#pragma unroll 4
    for (int it = 0; it < 64; it++) {
        int idx = it * 128 + tid;
        int r = idx >> 6;                // 0..127
        int c2 = (idx & 63) * 2;         // even col
        float v0 = C[r * 128 + (c2 ^ (r & 31))];
        float v1 = C[r * 128 + ((c2 + 1) ^ (r & 31))];
        *reinterpret_cast<__half2*>(
            &g_sim16[(size_t)(tileRow + r) * NB + tileCol + c2]) =
            __floats2half2_rn(v0, v1);
    }
    if (blockIdx.x != blockIdx.y) {
#pragma unroll 4
        for (int it = 0; it < 64; it++) {
            int idx = it * 128 + tid;
            int j = idx >> 6;            // mirror row offset 0..127
            int i2 = (idx & 63) * 2;     // even mirror col
            float v0 = C[i2 * 128 + (j ^ (i2 & 31))];
            float v1 = C[(i2 + 1) * 128 + (j ^ ((i2 + 1) & 31))];
            *reinterpret_cast<__half2*>(
                &g_sim16[(size_t)(tileCol + j) * NB + tileRow + i2]) =
                __floats2half2_rn(v0, v1);
        }
    }
}

// -------------------- kernel 2: per-row reductions + fused final reduce -------------
__global__ void __launch_bounds__(256) row_kernel(float* __restrict__ out) {
    const int row = blockIdx.x;
    const int tid = threadIdx.x;
    const int lid = tid & 31;
    const int wrp = tid >> 5;

    __shared__ float wmx[8], wns[8], wps[8];
    __shared__ int   wnn[8], wnp[8];
    __shared__ float s_maxneg, s_negsum;
    __shared__ int   s_nneg;
    __shared__ int   s_last;

    const uint4* srow = reinterpret_cast<const uint4*>(g_sim16 + (size_t)row * NB);
    const uint2* lab2 = reinterpret_cast<const uint2*>(g_lab8);
    const int rl = g_labels[row];
    const uint32_t rl4 = (uint32_t)(rl & 0xFF) * 0x01010101u;

    float s[16];
    uint32_t m_pc = 0;   // bit q: label == rl && s < 1-eps (pos candidate)

    float mx = -INFINITY, ns = 0.0f;
    int nn = 0;

#pragma unroll
    for (int it = 0; it < 2; it++) {
        uint4 raw = srow[it * 256 + tid];            // 8 halves
        uint2 lw = lab2[it * 256 + tid];             // 8 byte-labels
        uint32_t eq0 = __vcmpeq4(lw.x, rl4);         // 0xFF per matching byte
        uint32_t eq1 = __vcmpeq4(lw.y, rl4);
        nn += __popc(~eq0 & 0x01010101u) + __popc(~eq1 & 0x01010101u);
        float2 f0 = __half22float2(*reinterpret_cast<const __half2*>(&raw.x));
        float2 f1 = __half22float2(*reinterpret_cast<const __half2*>(&raw.y));
        float2 f2 = __half22float2(*reinterpret_cast<const __half2*>(&raw.z));
        float2 f3 = __half22float2(*reinterpret_cast<const __half2*>(&raw.w));
        float sv[8] = {f0.x, f0.y, f1.x, f1.y, f2.x, f2.y, f3.x, f3.y};
#pragma unroll
        for (int q = 0; q < 8; q++) {
            s[it * 8 + q] = sv[q];
            uint32_t eqw = (q < 4) ? eq0 : eq1;
            bool iseq = (eqw >> ((q & 3) * 8)) & 1;
            if (!iseq) {
                ns += __expf(SCALE_NEG * sv[q]);
                mx = fmaxf(mx, sv[q]);
            } else if (sv[q] < (1.0f - EPS_C)) {
                m_pc |= (1u << (it * 8 + q));
            }
        }
    }

#pragma unroll
    for (int o = 16; o > 0; o >>= 1) {
        mx = fmaxf(mx, __shfl_xor_sync(0xFFFFFFFFu, mx, o));
        ns += __shfl_xor_sync(0xFFFFFFFFu, ns, o);
        nn += __shfl_xor_sync(0xFFFFFFFFu, nn, o);
    }
    if (lid == 0) { wmx[wrp] = mx; wns[wrp] = ns; wnn[wrp] = nn; }
    __syncthreads();
    if (wrp == 0) {
        float m2 = (lid < 8) ? wmx[lid] : -INFINITY;
        float n2 = (lid < 8) ? wns[lid] : 0.0f;
        int   c2 = (lid < 8) ? wnn[lid] : 0;
#pragma unroll
        for (int o = 4; o > 0; o >>= 1) {
            m2 = fmaxf(m2, __shfl_xor_sync(0xFFFFFFFFu, m2, o));
            n2 += __shfl_xor_sync(0xFFFFFFFFu, n2, o);
            c2 += __shfl_xor_sync(0xFFFFFFFFu, c2, o);
        }
        if (lid == 0) { s_maxneg = m2; s_negsum = n2; s_nneg = c2; }
    }
    __syncthreads();

    const float maxneg = s_maxneg;

    float ps = 0.0f;
    int np = 0;
    uint32_t m = m_pc;
#pragma unroll
    for (int q = 0; q < 16; q++) {
        if (m & (1u << q)) {
            float sv = s[q];
            if ((sv - MARGIN) < maxneg) {
                np++;
                ps += __expf(-SCALE_POS * sv);
            }
        }
    }
#pragma unroll
    for (int o = 16; o > 0; o >>= 1) {
        ps += __shfl_xor_sync(0xFFFFFFFFu, ps, o);
        np += __shfl_xor_sync(0xFFFFFFFFu, np, o);
    }
    if (lid == 0) { wps[wrp] = ps; wnp[wrp] = np; }
    __syncthreads();
    if (tid == 0) {
        float pos_sum = 0.0f;
        int n_pos = 0;
#pragma unroll
        for (int w = 0; w < 8; w++) { pos_sum += wps[w]; n_pos += wnp[w]; }
        float neg_sum = s_negsum;
        int n_neg = s_nneg;
        float pos_loss = (1.0f / SCALE_POS) *
            __logf((pos_sum + __expf(-SCALE_POS * THRESH1)) / (float)(n_pos + 1));
        float neg_loss = (1.0f / SCALE_NEG) *
            __logf((neg_sum + __expf(SCALE_NEG * THRESH2)) / (float)(n_neg + 1));
        float per_row = __logf(5.33f + __expf(pos_loss + neg_loss));
        g_row[row] = (n_neg >= 1 && n_pos >= 1) ? per_row : 0.0f;
        __threadfence();
        int t = atomicAdd(&g_ticket, 1);
        s_last = (t == NB - 1) ? 1 : 0;
    }
    __syncthreads();

    // last CTA to finish: deterministic fixed-order final reduction
    if (s_last) {
        __shared__ float wsum[8];
        const float4* r4 = reinterpret_cast<const float4*>(g_row);
        float acc4 = 0.0f;
#pragma unroll
        for (int it = 0; it < 4; it++) {
            float4 v = r4[it * 256 + tid];
            acc4 += (v.x + v.y) + (v.z + v.w);
        }
#pragma unroll
        for (int o = 16; o > 0; o >>= 1)
            acc4 += __shfl_xor_sync(0xFFFFFFFFu, acc4, o);
        if (lid == 0) wsum[wrp] = acc4;
        __syncthreads();
        if (tid == 0) {
            float t = 0.0f;
#pragma unroll
            for (int w = 0; w < 8; w++) t += wsum[w];
            out[0] = t * (1.0f / (float)NB);
            g_ticket = 0;                 // reset for next graph replay
        }
    }
}

// ---------------------------------------------------------------------------
extern "C" void kernel_launch(void* const* d_in, const int* in_sizes, int n_in,
                              void* d_out, int out_size) {
    const float* feats = (const float*)d_in[0];
    const int* labels = (const int*)d_in[1];
    float* out = (float*)d_out;

    cudaFuncSetAttribute(gemm_mma_kernel,
                         cudaFuncAttributeMaxDynamicSharedMemorySize, DYNSMEM);

    labels_kernel<<<1, 256>>>(labels);
    gemm_mma_kernel<<<dim3(32, 32), 128, DYNSMEM>>>(feats);
    row_kernel<<<NB, 256>>>(out);
}

// round 17
// speedup vs baseline: 1.1026x; 1.0349x over previous
#include <cuda_runtime.h>
#include <cuda_fp16.h>
#include <math.h>
#include <stdint.h>

// Problem constants (fixed by the reference: B=4096, D=1024, N_CLASSES=64)
#define NB 4096
#define ND 1024

#define MARGIN    0.09f
#define SCALE_POS 2.0f
#define SCALE_NEG 40.0f
#define EPS_C     1e-5f
#define THRESH1   0.501f
#define THRESH2   0.531f

// -------------------- device scratch (no runtime allocation) --------------------
__device__ __half   g_sim16[(size_t)NB * NB];  // 32 MB similarity matrix (fp16)
__device__ int      g_labels[NB];
__device__ uint32_t g_lab8[NB / 4];            // byte-packed labels (4 per word)
__device__ float    g_row[NB];
__device__ int      g_ticket;                  // last-block ticket (self-resetting)

// -------------------- PTX helpers (plain sm_80 features only) --------------------
__device__ __forceinline__ uint32_t smem_u32(const void* p) {
    uint32_t a;
    asm("{ .reg .u64 t; cvta.to.shared.u64 t, %1; cvt.u32.u64 %0, t; }" : "=r"(a) : "l"(p));
    return a;
}
__device__ __forceinline__ void cp16(uint32_t s, const void* g) {
    asm volatile("cp.async.cg.shared.global [%0], [%1], 16;" :: "r"(s), "l"(g));
}
#define CP_COMMIT() asm volatile("cp.async.commit_group;" ::: "memory")
#define CP_WAIT2()  asm volatile("cp.async.wait_group 2;" ::: "memory")

__device__ __forceinline__ void ldsm4(uint32_t* r, uint32_t addr) {
    asm volatile("ldmatrix.sync.aligned.m8n8.x4.shared.b16 {%0,%1,%2,%3}, [%4];"
                 : "=r"(r[0]), "=r"(r[1]), "=r"(r[2]), "=r"(r[3]) : "r"(addr));
}
// m16n8k8 tf32: A = 4 regs, B = 2 regs, fp32 accum.
// Operands carry RAW fp32 bits -> hardware truncates to tf32 (error analyzed OK).
__device__ __forceinline__ void mma_tf32(float* d, const uint32_t* a,
                                         uint32_t b0, uint32_t b1) {
    asm volatile(
        "mma.sync.aligned.m16n8k8.row.col.f32.tf32.tf32.f32 "
        "{%0,%1,%2,%3}, {%4,%5,%6,%7}, {%8,%9}, {%0,%1,%2,%3};"
        : "+f"(d[0]), "+f"(d[1]), "+f"(d[2]), "+f"(d[3])
        : "r"(a[0]), "r"(a[1]), "r"(a[2]), "r"(a[3]), "r"(b0), "r"(b1));
}

// -------------------- kernel 1: mma.sync tf32 symmetric GEMM + hidden labels -------
// sim = F * F^T single pass, reading feats (raw fp32 -> tf32 truncation) directly.
// 128x128 tiles, upper triangle + mirror; 4 warps x (64x64); BK=32 f32;
// 3-stage cp.async pipeline; fp16 output stores.
// Dead CTA (bx=0, by=1) performs label detect/normalize/byte-pack, fully
// overlapped with the GEMM wave (labels are consumed only by row_kernel).
#define STAGE_BYTES 32768          // A 16KB + B 16KB
#define NCHUNK 32
#define DYNSMEM (3 * STAGE_BYTES)  // 96 KB (epilogue reuses 64 KB of it)

__device__ __forceinline__ void load_chunk(const uint8_t* base, int c, uint32_t stage,
                                           int rowA, int rowB, int tid) {
    size_t k0 = (size_t)c * 128;     // byte offset within 4096B row
    uint32_t sB = stage + 16384;
#pragma unroll
    for (int j = 0; j < 8; j++) {
        int u = (j << 7) + tid;          // 0..1023 16B units per operand
        int r = u >> 3;                  // row 0..127
        int ch = u & 7;                  // 16B chunk within 128B row
        uint32_t off = (uint32_t)((r << 7) + (ch << 4));
        uint32_t sw = off ^ ((off >> 3) & 0x70);
        cp16(stage + sw, base + (size_t)(rowA + r) * 4096 + k0 + (ch << 4));
        cp16(sB + sw,    base + (size_t)(rowB + r) * 4096 + k0 + (ch << 4));
    }
}

__global__ void __launch_bounds__(128, 2) gemm_mma_kernel(const float* __restrict__ feats,
                                                          const int* __restrict__ lab) {
    extern __shared__ char dsm[];
    if ((int)blockIdx.x < (int)blockIdx.y) {
        // ---- labels path on one dead CTA (bx=0, by=1); others exit ----
        if (blockIdx.x == 0 && blockIdx.y == 1) {
            __shared__ int sred[128];
            __shared__ int s_is64;
            int tid = threadIdx.x;
            int acc = 0;
            for (int i = tid; i < 2048; i += 128) acc |= lab[2 * i + 1];
            sred[tid] = acc;
            __syncthreads();
            for (int o = 64; o > 0; o >>= 1) {
                if (tid < o) sred[tid] |= sred[tid + o];
                __syncthreads();
            }
            if (tid == 0) s_is64 = (sred[0] == 0) ? 1 : 0;
            __syncthreads();
            int is64 = s_is64;
            for (int i = tid; i < NB; i += 128)
                g_labels[i] = is64 ? lab[2 * i] : lab[i];
            __syncthreads();
            for (int w = tid; w < NB / 4; w += 128) {
                uint32_t p = (uint32_t)(g_labels[4 * w] & 0xFF)
                           | ((uint32_t)(g_labels[4 * w + 1] & 0xFF) << 8)
                           | ((uint32_t)(g_labels[4 * w + 2] & 0xFF) << 16)
                           | ((uint32_t)(g_labels[4 * w + 3] & 0xFF) << 24);
                g_lab8[w] = p;
            }
        }
        return;
    }
    const uint8_t* base = reinterpret_cast<const uint8_t*>(feats);
    const int tid = threadIdx.x;
    const int lid = tid & 31;
    const int wid = tid >> 5;            // 0..3
    const int tileRow = blockIdx.y * 128;
    const int tileCol = blockIdx.x * 128;

    uint32_t SB = (smem_u32(dsm) + 127u) & ~127u;

    // warp tile: 64 (M) x 64 (N); warp grid 2 x 2
    const int mRow0 = (wid >> 1) * 64;
    const int nCol0 = (wid & 1) * 64;

    // ldmatrix lane addressing (b16-view of f32 tiles)
    const int aRow  = lid & 15;
    const int aKoff = ((lid >> 4) & 1) * 16;         // bytes
    const int bRow  = (lid & 7) + ((lid >> 4) << 3);
    const int bKoff = ((lid >> 3) & 1) * 16;         // bytes

    float acc[4][8][4];
#pragma unroll
    for (int mt = 0; mt < 4; mt++)
#pragma unroll
        for (int nt = 0; nt < 8; nt++)
#pragma unroll
            for (int q = 0; q < 4; q++) acc[mt][nt][q] = 0.0f;

    load_chunk(base, 0, SB + 0 * STAGE_BYTES, tileRow, tileCol, tid); CP_COMMIT();
    load_chunk(base, 1, SB + 1 * STAGE_BYTES, tileRow, tileCol, tid); CP_COMMIT();

    for (int c = 0; c < NCHUNK; c++) {
        if (c + 2 < NCHUNK)
            load_chunk(base, c + 2, SB + ((c + 2) % 3) * STAGE_BYTES,
                       tileRow, tileCol, tid);
        CP_COMMIT();
        CP_WAIT2();
        __syncthreads();

        uint32_t sa = SB + (c % 3) * STAGE_BYTES;
        uint32_t sbm = sa + 16384;
#pragma unroll
        for (int kk = 0; kk < 4; kk++) {             // 4 x k8 within BK=32 f32
            uint32_t afrag[4][4];
#pragma unroll
            for (int mt = 0; mt < 4; mt++) {
                uint32_t off = (uint32_t)((mRow0 + mt * 16 + aRow) * 128 +
                                          aKoff + kk * 32);
                ldsm4(afrag[mt], sa + (off ^ ((off >> 3) & 0x70)));
            }
            uint32_t bfrag[4][4];                     // each g: n16 (two n8 frags)
#pragma unroll
            for (int g = 0; g < 4; g++) {
                uint32_t off = (uint32_t)((nCol0 + g * 16 + bRow) * 128 +
                                          bKoff + kk * 32);
                ldsm4(bfrag[g], sbm + (off ^ ((off >> 3) & 0x70)));
            }
#pragma unroll
            for (int mt = 0; mt < 4; mt++)
#pragma unroll
                for (int g = 0; g < 4; g++) {
                    mma_tf32(acc[mt][g * 2],     afrag[mt], bfrag[g][0], bfrag[g][1]);
                    mma_tf32(acc[mt][g * 2 + 1], afrag[mt], bfrag[g][2], bfrag[g][3]);
                }
        }
        __syncthreads();
    }

    // ---- epilogue: fragments -> XOR-swizzled SMEM -> fp16 normal + mirror stores ----
    float* C = reinterpret_cast<float*>(dsm);
#pragma unroll
    for (int mt = 0; mt < 4; mt++) {
        int r0 = mRow0 + mt * 16 + (lid >> 2);
#pragma unroll
        for (int nt = 0; nt < 8; nt++) {
            int cc = nCol0 + nt * 8 + (lid & 3) * 2;
            C[r0 * 128 + (cc ^ (r0 & 31))]       = acc[mt][nt][0];
            C[r0 * 128 + ((cc + 1) ^ (r0 & 31))] = acc[mt][nt][1];
            int r1 = r0 + 8;
            C[r1 * 128 + (cc ^ (r1 & 31))]       = acc[mt][nt][2];
            C[r1 * 128 + ((cc + 1) ^ (r1 & 31))] = acc[mt][nt][3];
        }
    }
    __syncthreads();

    // normal store: 8192 half2 units, 64 per thread
#pragma unroll 4
    for (int it = 0; it < 64; it++) {
        int idx = it * 128 + tid;
        int r = idx >> 6;                // 0..127
        int c2 = (idx & 63) * 2;         // even col
        float v0 = C[r * 128 + (c2 ^ (r & 31))];
        float v1 = C[r * 128 + ((c2 + 1) ^ (r & 31))];
        *reinterpret_cast<__half2*>(
            &g_sim16[(size_t)(tileRow + r) * NB + tileCol + c2]) =
            __floats2half2_rn(v0, v1);
    }
    if (blockIdx.x != blockIdx.y) {
#pragma unroll 4
        for (int it = 0; it < 64; it++) {
            int idx = it * 128 + tid;
            int j = idx >> 6;            // mirror row offset 0..127
            int i2 = (idx & 63) * 2;     // even mirror col
            float v0 = C[i2 * 128 + (j ^ (i2 & 31))];
            float v1 = C[(i2 + 1) * 128 + (j ^ ((i2 + 1) & 31))];
            *reinterpret_cast<__half2*>(
                &g_sim16[(size_t)(tileCol + j) * NB + tileRow + i2]) =
                __floats2half2_rn(v0, v1);
        }
    }
}

// -------------------- kernel 2: per-row reductions + fused final reduce -------------
__global__ void __launch_bounds__(256) row_kernel(float* __restrict__ out) {
    const int row = blockIdx.x;
    const int tid = threadIdx.x;
    const int lid = tid & 31;
    const int wrp = tid >> 5;

    __shared__ float wmx[8], wns[8], wps[8];
    __shared__ int   wnn[8], wnp[8];
    __shared__ float s_maxneg, s_negsum;
    __shared__ int   s_nneg;
    __shared__ int   s_last;

    const uint4* srow = reinterpret_cast<const uint4*>(g_sim16 + (size_t)row * NB);
    const uint2* lab2 = reinterpret_cast<const uint2*>(g_lab8);
    const int rl = g_labels[row];
    const uint32_t rl4 = (uint32_t)(rl & 0xFF) * 0x01010101u;

    float s[16];
    uint32_t m_pc = 0;   // bit q: label == rl && s < 1-eps (pos candidate)

    float mx = -INFINITY, ns = 0.0f;
    int nn = 0;

#pragma unroll
    for (int it = 0; it < 2; it++) {
        uint4 raw = srow[it * 256 + tid];            // 8 halves
        uint2 lw = lab2[it * 256 + tid];             // 8 byte-labels
        uint32_t eq0 = __vcmpeq4(lw.x, rl4);         // 0xFF per matching byte
        uint32_t eq1 = __vcmpeq4(lw.y, rl4);
        nn += __popc(~eq0 & 0x01010101u) + __popc(~eq1 & 0x01010101u);
        float2 f0 = __half22float2(*reinterpret_cast<const __half2*>(&raw.x));
        float2 f1 = __half22float2(*reinterpret_cast<const __half2*>(&raw.y));
        float2 f2 = __half22float2(*reinterpret_cast<const __half2*>(&raw.z));
        float2 f3 = __half22float2(*reinterpret_cast<const __half2*>(&raw.w));
        float sv[8] = {f0.x, f0.y, f1.x, f1.y, f2.x, f2.y, f3.x, f3.y};
#pragma unroll
        for (int q = 0; q < 8; q++) {
            s[it * 8 + q] = sv[q];
            uint32_t eqw = (q < 4) ? eq0 : eq1;
            bool iseq = (eqw >> ((q & 3) * 8)) & 1;
            if (!iseq) {
                ns += __expf(SCALE_NEG * sv[q]);
                mx = fmaxf(mx, sv[q]);
            } else if (sv[q] < (1.0f - EPS_C)) {
                m_pc |= (1u << (it * 8 + q));
            }
        }
    }

#pragma unroll
    for (int o = 16; o > 0; o >>= 1) {
        mx = fmaxf(mx, __shfl_xor_sync(0xFFFFFFFFu, mx, o));
        ns += __shfl_xor_sync(0xFFFFFFFFu, ns, o);
        nn += __shfl_xor_sync(0xFFFFFFFFu, nn, o);
    }
    if (lid == 0) { wmx[wrp] = mx; wns[wrp] = ns; wnn[wrp] = nn; }
    __syncthreads();
    if (wrp == 0) {
        float m2 = (lid < 8) ? wmx[lid] : -INFINITY;
        float n2 = (lid < 8) ? wns[lid] : 0.0f;
        int   c2 = (lid < 8) ? wnn[lid] : 0;
#pragma unroll
        for (int o = 4; o > 0; o >>= 1) {
            m2 = fmaxf(m2, __shfl_xor_sync(0xFFFFFFFFu, m2, o));
            n2 += __shfl_xor_sync(0xFFFFFFFFu, n2, o);
            c2 += __shfl_xor_sync(0xFFFFFFFFu, c2, o);
        }
        if (lid == 0) { s_maxneg = m2; s_negsum = n2; s_nneg = c2; }
    }
    __syncthreads();

    const float maxneg = s_maxneg;

    float ps = 0.0f;
    int np = 0;
    uint32_t m = m_pc;
#pragma unroll
    for (int q = 0; q < 16; q++) {
        if (m & (1u << q)) {
            float sv = s[q];
            if ((sv - MARGIN) < maxneg) {
                np++;
                ps += __expf(-SCALE_POS * sv);
            }
        }
    }
#pragma unroll
    for (int o = 16; o > 0; o >>= 1) {
        ps += __shfl_xor_sync(0xFFFFFFFFu, ps, o);
        np += __shfl_xor_sync(0xFFFFFFFFu, np, o);
    }
    if (lid == 0) { wps[wrp] = ps; wnp[wrp] = np; }
    __syncthreads();
    if (tid == 0) {
        float pos_sum = 0.0f;
        int n_pos = 0;
#pragma unroll
        for (int w = 0; w < 8; w++) { pos_sum += wps[w]; n_pos += wnp[w]; }
        float neg_sum = s_negsum;
        int n_neg = s_nneg;
        float pos_loss = (1.0f / SCALE_POS) *
            __logf((pos_sum + __expf(-SCALE_POS * THRESH1)) / (float)(n_pos + 1));
        float neg_loss = (1.0f / SCALE_NEG) *
            __logf((neg_sum + __expf(SCALE_NEG * THRESH2)) / (float)(n_neg + 1));
        float per_row = __logf(5.33f + __expf(pos_loss + neg_loss));
        g_row[row] = (n_neg >= 1 && n_pos >= 1) ? per_row : 0.0f;
        __threadfence();
        int t = atomicAdd(&g_ticket, 1);
        s_last = (t == NB - 1) ? 1 : 0;
    }
    __syncthreads();

    // last CTA to finish: deterministic fixed-order final reduction
    if (s_last) {
        __shared__ float wsum[8];
        const float4* r4 = reinterpret_cast<const float4*>(g_row);
        float acc4 = 0.0f;
#pragma unroll
        for (int it = 0; it < 4; it++) {
            float4 v = r4[it * 256 + tid];
            acc4 += (v.x + v.y) + (v.z + v.w);
        }
#pragma unroll
        for (int o = 16; o > 0; o >>= 1)
            acc4 += __shfl_xor_sync(0xFFFFFFFFu, acc4, o);
        if (lid == 0) wsum[wrp] = acc4;
        __syncthreads();
        if (tid == 0) {
            float t = 0.0f;
#pragma unroll
            for (int w = 0; w < 8; w++) t += wsum[w];
            out[0] = t * (1.0f / (float)NB);
            g_ticket = 0;                 // reset for next graph replay
        }
    }
}

// ---------------------------------------------------------------------------
extern "C" void kernel_launch(void* const* d_in, const int* in_sizes, int n_in,
                              void* d_out, int out_size) {
    const float* feats = (const float*)d_in[0];
    const int* labels = (const int*)d_in[1];
    float* out = (float*)d_out;

    cudaFuncSetAttribute(gemm_mma_kernel,
                         cudaFuncAttributeMaxDynamicSharedMemorySize, DYNSMEM);

    gemm_mma_kernel<<<dim3(32, 32), 128, DYNSMEM>>>(feats, labels);
    row_kernel<<<NB, 256>>>(out);
}